// round 1
// baseline (speedup 1.0000x reference)
#include <cuda_runtime.h>
#include <math.h>

#define EMBD 512
#define NHEADS 8
#define HDIM 64
#define NDEPTH 6
#define NCONT 100
#define NCAT 28
#define NHID 682
#define BSZ 128
#define SEQ 129
#define NTOK (BSZ*SEQ)      /* 16512 */
#define QKVN (3*EMBD)       /* 1536  */
#define HID2 (2*NHID)       /* 1364  */
#define NBH (BSZ*NHEADS)    /* 1024  */

// ---------------- scratch (device globals; no allocation allowed) ----------
__device__ float g_h[NTOK*EMBD];
__device__ float g_xin[NTOK*EMBD];
__device__ float g_qkv[NTOK*QKVN];
__device__ float g_scores[(size_t)NBH*SEQ*SEQ];
__device__ float g_obuf[NTOK*EMBD];
__device__ float g_u[NTOK*HID2];
__device__ float g_r[NTOK*NHID];

// ---------------- tokenizer ------------------------------------------------
__global__ void tokenizer_kernel(const float* __restrict__ x,
                                 const float* __restrict__ tok_w,
                                 const float* __restrict__ tok_b,
                                 const float* __restrict__ cat_emb,
                                 float* __restrict__ h) {
    int t = blockIdx.x;            // token id 0..NTOK-1
    int b = t / SEQ, s = t % SEQ;
    int e0 = threadIdx.x;          // 128 threads, 4 elems each

    const float* src;
    float scale = 1.0f;
    const float* brow = nullptr;
    if (s == 0) {
        src = tok_w;               // row 0, scale 1, bias 0
    } else if (s <= NCONT) {
        src = tok_w + (size_t)s * EMBD;
        scale = x[(size_t)b * (NCAT + NCONT) + NCAT + (s - 1)];
        brow = tok_b + (size_t)(s - 1) * EMBD;
    } else {
        int c = s - (NCONT + 1);
        int idx = (int)x[(size_t)b * (NCAT + NCONT) + c] + 100 * c;
        src = cat_emb + (size_t)idx * EMBD;
        brow = tok_b + (size_t)(s - 1) * EMBD;
    }
    float* dst = h + (size_t)t * EMBD;
#pragma unroll
    for (int i = 0; i < 4; i++) {
        int e = e0 + i * 128;
        float v = src[e] * scale;
        if (brow) v += brow[e];
        dst[e] = v;
    }
}

// ---------------- layernorm (warp per row) ---------------------------------
__global__ void ln_kernel(const float* __restrict__ in,
                          const float* __restrict__ g,
                          const float* __restrict__ b,
                          float* __restrict__ out) {
    int row = blockIdx.x * 8 + threadIdx.y;
    if (row >= NTOK) return;
    const float* p = in + (size_t)row * EMBD;
    int lane = threadIdx.x;
    float v[16];
    float s = 0.f;
#pragma unroll
    for (int i = 0; i < 16; i++) { v[i] = p[lane + 32 * i]; s += v[i]; }
#pragma unroll
    for (int o = 16; o; o >>= 1) s += __shfl_xor_sync(0xffffffffu, s, o);
    float mean = s * (1.0f / EMBD);
    float vs = 0.f;
#pragma unroll
    for (int i = 0; i < 16; i++) { float d = v[i] - mean; vs += d * d; }
#pragma unroll
    for (int o = 16; o; o >>= 1) vs += __shfl_xor_sync(0xffffffffu, vs, o);
    float inv = rsqrtf(vs * (1.0f / EMBD) + 1e-5f);
    float* q = out + (size_t)row * EMBD;
#pragma unroll
    for (int i = 0; i < 16; i++) {
        int e = lane + 32 * i;
        q[e] = (v[i] - mean) * inv * g[e] + b[e];
    }
}

// ---------------- tiled SGEMM: C = A[MxK] @ B[KxN] + bias (+residual) ------
template <int RES>
__global__ void __launch_bounds__(256)
sgemm_kernel(const float* __restrict__ A, const float* __restrict__ Bm,
             const float* __restrict__ bias, const float* __restrict__ res,
             float* __restrict__ C, int M, int N, int K) {
    const int BM = 128, BN = 128, BK = 16;
    __shared__ float As[BK][BM + 1];
    __shared__ float Bs[BK][BN];
    int m0 = blockIdx.x * BM, n0 = blockIdx.y * BN;
    int tid = threadIdx.x;
    int tm = (tid / 16) * 8, tn = (tid % 16) * 8;
    float acc[8][8];
#pragma unroll
    for (int i = 0; i < 8; i++)
#pragma unroll
        for (int j = 0; j < 8; j++) acc[i][j] = 0.f;

    for (int k0 = 0; k0 < K; k0 += BK) {
#pragma unroll
        for (int i = tid; i < BM * BK; i += 256) {
            int r = i / BK, c = i % BK;
            float v = 0.f;
            if (m0 + r < M && k0 + c < K) v = A[(size_t)(m0 + r) * K + k0 + c];
            As[c][r] = v;
        }
#pragma unroll
        for (int i = tid; i < BK * BN; i += 256) {
            int kk = i / BN, n = i % BN;
            float v = 0.f;
            if (k0 + kk < K && n0 + n < N) v = Bm[(size_t)(k0 + kk) * N + n0 + n];
            Bs[kk][n] = v;
        }
        __syncthreads();
#pragma unroll
        for (int kk = 0; kk < BK; kk++) {
            float a[8], bb[8];
#pragma unroll
            for (int i = 0; i < 8; i++) a[i] = As[kk][tm + i];
            float4 b0 = *reinterpret_cast<const float4*>(&Bs[kk][tn]);
            float4 b1 = *reinterpret_cast<const float4*>(&Bs[kk][tn + 4]);
            bb[0] = b0.x; bb[1] = b0.y; bb[2] = b0.z; bb[3] = b0.w;
            bb[4] = b1.x; bb[5] = b1.y; bb[6] = b1.z; bb[7] = b1.w;
#pragma unroll
            for (int i = 0; i < 8; i++)
#pragma unroll
                for (int j = 0; j < 8; j++) acc[i][j] += a[i] * bb[j];
        }
        __syncthreads();
    }
#pragma unroll
    for (int i = 0; i < 8; i++) {
        int m = m0 + tm + i;
        if (m >= M) break;
#pragma unroll
        for (int j = 0; j < 8; j++) {
            int n = n0 + tn + j;
            if (n >= N) continue;
            float v = acc[i][j] + bias[n];
            if (RES) v += res[(size_t)m * N + n];
            C[(size_t)m * N + n] = v;
        }
    }
}

// ---------------- attention scores: q@k^T * sqrt(EMB) ----------------------
__global__ void scores_kernel(const float* __restrict__ qkv,
                              float* __restrict__ scores) {
    extern __shared__ float sm[];
    float* qs = sm;                 // [SEQ][65]
    float* ks = sm + SEQ * 65;      // [SEQ][65]
    int bh = blockIdx.x;
    int b = bh / NHEADS, h = bh % NHEADS;
    const float* base = qkv + (size_t)b * SEQ * QKVN + h * (3 * HDIM);
    int tid = threadIdx.x;
    for (int i = tid; i < SEQ * HDIM; i += 256) {
        int r = i / HDIM, d = i % HDIM;
        const float* row = base + (size_t)r * QKVN;
        qs[r * 65 + d] = row[d];
        ks[r * 65 + d] = row[HDIM + d];
    }
    __syncthreads();
    const float scale = 22.62741699796952f;  // sqrt(512)
    float* out = scores + (size_t)bh * SEQ * SEQ;
    for (int idx = tid; idx < SEQ * SEQ; idx += 256) {
        int i = idx / SEQ, j = idx % SEQ;
        const float* qi = qs + i * 65;
        const float* kj = ks + j * 65;
        float acc = 0.f;
#pragma unroll
        for (int d = 0; d < HDIM; d++) acc += qi[d] * kj[d];
        out[idx] = acc * scale;
    }
}

// ---------------- double softmax over rows of length SEQ -------------------
__global__ void softmax2_kernel(float* __restrict__ scores) {
    int row = blockIdx.x * 8 + threadIdx.y;
    if (row >= NBH * SEQ) return;
    float* p = scores + (size_t)row * SEQ;
    int lane = threadIdx.x;
    float v[5];
    int cnt = 0;
    float mx = -1e30f;
    for (int j = lane; j < SEQ; j += 32) { v[cnt] = p[j]; mx = fmaxf(mx, v[cnt]); cnt++; }
#pragma unroll
    for (int o = 16; o; o >>= 1) mx = fmaxf(mx, __shfl_xor_sync(0xffffffffu, mx, o));
    float s = 0.f;
    for (int c = 0; c < cnt; c++) { v[c] = __expf(v[c] - mx); s += v[c]; }
#pragma unroll
    for (int o = 16; o; o >>= 1) s += __shfl_xor_sync(0xffffffffu, s, o);
    float inv = 1.0f / s;
    mx = -1e30f;
    for (int c = 0; c < cnt; c++) { v[c] *= inv; mx = fmaxf(mx, v[c]); }
#pragma unroll
    for (int o = 16; o; o >>= 1) mx = fmaxf(mx, __shfl_xor_sync(0xffffffffu, mx, o));
    s = 0.f;
    for (int c = 0; c < cnt; c++) { v[c] = __expf(v[c] - mx); s += v[c]; }
#pragma unroll
    for (int o = 16; o; o >>= 1) s += __shfl_xor_sync(0xffffffffu, s, o);
    inv = 1.0f / s;
    cnt = 0;
    for (int j = lane; j < SEQ; j += 32) { p[j] = v[cnt] * inv; cnt++; }
}

// ---------------- attn @ v, written in [B,S,H*HD] layout -------------------
__global__ void av_kernel(const float* __restrict__ qkv,
                          const float* __restrict__ scores,
                          float* __restrict__ obuf) {
    extern __shared__ float sm[];
    float* attn = sm;               // [SEQ][SEQ]
    float* vs = sm + SEQ * SEQ;     // [SEQ][HDIM]
    int bh = blockIdx.x;
    int b = bh / NHEADS, h = bh % NHEADS;
    const float* vbase = qkv + (size_t)b * SEQ * QKVN + h * (3 * HDIM) + 2 * HDIM;
    int tid = threadIdx.y * 64 + threadIdx.x;
    const float* srow = scores + (size_t)bh * SEQ * SEQ;
    for (int i = tid; i < SEQ * SEQ; i += 256) attn[i] = srow[i];
    for (int i = tid; i < SEQ * HDIM; i += 256) {
        int r = i / HDIM, d = i % HDIM;
        vs[r * HDIM + d] = vbase[(size_t)r * QKVN + d];
    }
    __syncthreads();
    int d = threadIdx.x;            // 0..63
    for (int i = threadIdx.y; i < SEQ; i += 4) {
        const float* ar = attn + i * SEQ;
        float acc = 0.f;
        for (int j = 0; j < SEQ; j++) acc += ar[j] * vs[j * HDIM + d];
        obuf[((size_t)b * SEQ + i) * EMBD + h * HDIM + d] = acc;
    }
}

// ---------------- ReGLU ----------------------------------------------------
__global__ void reglu_kernel(const float* __restrict__ u, float* __restrict__ r) {
    int n = blockIdx.x;
    const float* un = u + (size_t)n * HID2;
    float* rn = r + (size_t)n * NHID;
    for (int j = threadIdx.x; j < NHID; j += 256)
        rn[j] = un[j] * fmaxf(un[NHID + j], 0.f);
}

// ---------------- extract CLS ----------------------------------------------
__global__ void extract_kernel(const float* __restrict__ h, float* __restrict__ out) {
    int b = blockIdx.x;
    int e = threadIdx.x;
    out[(size_t)b * EMBD + e] = h[(size_t)b * SEQ * EMBD + e];
}

// ---------------- host -----------------------------------------------------
extern "C" void kernel_launch(void* const* d_in, const int* in_sizes, int n_in,
                              void* d_out, int out_size) {
    (void)in_sizes; (void)n_in; (void)out_size;
    const float* x       = (const float*)d_in[0];
    const float* tok_w   = (const float*)d_in[1];
    const float* tok_b   = (const float*)d_in[2];
    const float* cat_emb = (const float*)d_in[3];
    const float* Wqkv    = (const float*)d_in[4];
    const float* bqkv    = (const float*)d_in[5];
    const float* Wout    = (const float*)d_in[6];
    const float* bout    = (const float*)d_in[7];
    const float* W0      = (const float*)d_in[8];
    const float* b0      = (const float*)d_in[9];
    const float* W1      = (const float*)d_in[10];
    const float* b1      = (const float*)d_in[11];
    const float* ln0_g   = (const float*)d_in[12];
    const float* ln0_b   = (const float*)d_in[13];
    const float* ln1_g   = (const float*)d_in[14];
    const float* ln1_b   = (const float*)d_in[15];
    float* out = (float*)d_out;

    float *ph, *pxin, *pqkv, *pscores, *pobuf, *pu, *pr;
    cudaGetSymbolAddress((void**)&ph, g_h);
    cudaGetSymbolAddress((void**)&pxin, g_xin);
    cudaGetSymbolAddress((void**)&pqkv, g_qkv);
    cudaGetSymbolAddress((void**)&pscores, g_scores);
    cudaGetSymbolAddress((void**)&pobuf, g_obuf);
    cudaGetSymbolAddress((void**)&pu, g_u);
    cudaGetSymbolAddress((void**)&pr, g_r);

    const int SCORES_SMEM = 2 * SEQ * 65 * 4;                  // 67080 B
    const int AV_SMEM = (SEQ * SEQ + SEQ * HDIM) * 4;          // 99588 B
    cudaFuncSetAttribute(scores_kernel,
                         cudaFuncAttributeMaxDynamicSharedMemorySize, SCORES_SMEM);
    cudaFuncSetAttribute(av_kernel,
                         cudaFuncAttributeMaxDynamicSharedMemorySize, AV_SMEM);

    tokenizer_kernel<<<NTOK, 128>>>(x, tok_w, tok_b, cat_emb, ph);

    for (int L = 0; L < NDEPTH; L++) {
        const float* xin_ptr;
        if (L == 0) {
            xin_ptr = ph;
        } else {
            ln_kernel<<<NTOK / 8, dim3(32, 8)>>>(ph, ln0_g + L * EMBD,
                                                 ln0_b + L * EMBD, pxin);
            xin_ptr = pxin;
        }
        // qkv = xin @ Wqkv + bqkv
        sgemm_kernel<0><<<dim3(NTOK / 128, QKVN / 128), 256>>>(
            xin_ptr, Wqkv + (size_t)L * EMBD * QKVN, bqkv + (size_t)L * QKVN,
            nullptr, pqkv, NTOK, QKVN, EMBD);
        scores_kernel<<<NBH, 256, SCORES_SMEM>>>(pqkv, pscores);
        softmax2_kernel<<<NBH * SEQ / 8, dim3(32, 8)>>>(pscores);
        av_kernel<<<NBH, dim3(64, 4), AV_SMEM>>>(pqkv, pscores, pobuf);
        // h = h + obuf @ Wout + bout
        sgemm_kernel<1><<<dim3(NTOK / 128, EMBD / 128), 256>>>(
            pobuf, Wout + (size_t)L * EMBD * EMBD, bout + (size_t)L * EMBD,
            ph, ph, NTOK, EMBD, EMBD);
        // FFN
        ln_kernel<<<NTOK / 8, dim3(32, 8)>>>(ph, ln1_g + L * EMBD,
                                             ln1_b + L * EMBD, pxin);
        sgemm_kernel<0><<<dim3(NTOK / 128, (HID2 + 127) / 128), 256>>>(
            pxin, W0 + (size_t)L * EMBD * HID2, b0 + (size_t)L * HID2,
            nullptr, pu, NTOK, HID2, EMBD);
        reglu_kernel<<<NTOK, 256>>>(pu, pr);
        sgemm_kernel<1><<<dim3(NTOK / 128, EMBD / 128), 256>>>(
            pr, W1 + (size_t)L * NHID * EMBD, b1 + (size_t)L * EMBD,
            ph, ph, NTOK, EMBD, NHID);
    }
    extract_kernel<<<BSZ, EMBD>>>(ph, out);
}

// round 3
// speedup vs baseline: 1.9007x; 1.9007x over previous
#include <cuda_runtime.h>
#include <cuda_bf16.h>
#include <cstdint>
#include <math.h>

#define EMBD 512
#define NHEADS 8
#define HDIM 64
#define NDEPTH 6
#define NCONT 100
#define NCAT 28
#define NHID 682
#define BSZ 128
#define SEQ 129
#define NTOK (BSZ*SEQ)      /* 16512 */
#define QKVN (3*EMBD)       /* 1536  */
#define HID2 (2*NHID)       /* 1364  */
#define NBH (BSZ*NHEADS)    /* 1024  */

#define KPAD_E 512          /* padded K for EMB-K GEMMs */
#define KPAD_H 704          /* padded K for NHID-K GEMM */
#define W0_NPAD 1536

// ---------------- scratch (device globals) ---------------------------------
__device__ float g_h[NTOK*EMBD];
__device__ float g_qkv[NTOK*QKVN];
__device__ float g_scores[(size_t)NBH*SEQ*SEQ];
__device__ float g_u[NTOK*HID2];
__device__ __nv_bfloat16 g_a2[(size_t)NTOK*(2*KPAD_H)];          // [M, 2*Kpad]
// per-layer converted weights: qkv | wout | w0 | w1
#define B2_QKV_SZ ((size_t)1536*1024)
#define B2_WOUT_SZ ((size_t)512*1024)
#define B2_W0_SZ ((size_t)W0_NPAD*1024)
#define B2_W1_SZ ((size_t)512*1408)
#define B2_LAYER (B2_QKV_SZ+B2_WOUT_SZ+B2_W0_SZ+B2_W1_SZ)
__device__ __nv_bfloat16 g_b2[B2_LAYER*NDEPTH];

// ---------------- helpers ---------------------------------------------------
__device__ __forceinline__ uint32_t smem_u32(const void* p) {
    uint32_t a;
    asm("{ .reg .u64 t; cvta.to.shared.u64 t, %1; cvt.u32.u64 %0, t; }" : "=r"(a) : "l"(p));
    return a;
}
#define LDSM4(r0, r1, r2, r3, addr) \
    asm volatile("ldmatrix.sync.aligned.m8n8.x4.shared.b16 {%0,%1,%2,%3}, [%4];" \
        : "=r"(r0), "=r"(r1), "=r"(r2), "=r"(r3) : "r"(addr))
#define MMA16816(d, a, b) \
    asm volatile("mma.sync.aligned.m16n8k16.row.col.f32.bf16.bf16.f32 " \
        "{%0,%1,%2,%3},{%4,%5,%6,%7},{%8,%9},{%0,%1,%2,%3};" \
        : "+f"((d)[0]), "+f"((d)[1]), "+f"((d)[2]), "+f"((d)[3]) \
        : "r"((a)[0]), "r"((a)[1]), "r"((a)[2]), "r"((a)[3]), "r"((b)[0]), "r"((b)[1]))

__device__ __forceinline__ void split_bf16(float v, __nv_bfloat16& hi, __nv_bfloat16& lo) {
    hi = __float2bfloat16(v);
    lo = __float2bfloat16(v - __bfloat162float(hi));
}

// ---------------- HMMA GEMM: C[M,Nact] = A2 @ B2^T (3-pass bf16 split) -----
// A2: [M, 2*Kpad] bf16 (hi|lo), B2: [Npad, 2*Kpad] bf16 (K-major, hi|lo)
#define APITCH 40            /* bf16 elems per smem row (80B, conflict-free) */
#define BUFB (128*APITCH*2)  /* bytes per buffer */
__global__ void __launch_bounds__(256)
gemm_mma(const __nv_bfloat16* __restrict__ A2, const __nv_bfloat16* __restrict__ B2,
         const float* __restrict__ bias, const float* __restrict__ res,
         float* __restrict__ C, int Nact, int Cs, int Kpad, int RES) {
    __shared__ __nv_bfloat16 As[2][128*APITCH];
    __shared__ __nv_bfloat16 Bs[2][128*APITCH];
    const int tid = threadIdx.x, lane = tid & 31, wid = tid >> 5;
    const int wm = wid & 1, wn = wid >> 1;            // warps 2(M) x 4(N)
    const int m0 = blockIdx.x * 128, n0 = blockIdx.y * 128;
    const int sA2 = 2 * Kpad;
    const int KC = Kpad >> 5;
    const int nsteps = 3 * KC;

    float acc[4][4][4];
#pragma unroll
    for (int a = 0; a < 4; a++)
#pragma unroll
        for (int b = 0; b < 4; b++)
#pragma unroll
            for (int c = 0; c < 4; c++) acc[a][b][c] = 0.f;

    // per-thread ldmatrix base addresses (buffer 0)
    const int q = lane >> 3, rr = lane & 7;
    const uint32_t aBase = smem_u32(&As[0][0]) +
        ((uint32_t)((wm * 64 + (q & 1) * 8 + rr) * APITCH + (q >> 1) * 8)) * 2;
    const uint32_t bBase = smem_u32(&Bs[0][0]) +
        ((uint32_t)((wn * 32 + (q >> 1) * 8 + rr) * APITCH + (q & 1) * 8)) * 2;

    const int r_ld = tid >> 2, seg = tid & 3;
    uint4 ra0, ra1, rb0, rb1;

#define LOADSTEP(i) do { \
    int pass = ((i) >= 2 * KC) ? 2 : (((i) >= KC) ? 1 : 0); \
    int kc = (i) - pass * KC; \
    int aO = ((pass == 2) ? Kpad : 0) + kc * 32; \
    int bO = ((pass == 1) ? Kpad : 0) + kc * 32; \
    const __nv_bfloat16* ap = A2 + (size_t)(m0 + r_ld) * sA2 + aO + seg * 8; \
    ra0 = *(const uint4*)ap; ra1 = *(const uint4*)(ap + (size_t)64 * sA2); \
    const __nv_bfloat16* bp = B2 + (size_t)(n0 + r_ld) * sA2 + bO + seg * 8; \
    rb0 = *(const uint4*)bp; rb1 = *(const uint4*)(bp + (size_t)64 * sA2); \
} while (0)

#define STORESTEP(bf) do { \
    *(uint4*)&As[bf][r_ld * APITCH + seg * 8] = ra0; \
    *(uint4*)&As[bf][(r_ld + 64) * APITCH + seg * 8] = ra1; \
    *(uint4*)&Bs[bf][r_ld * APITCH + seg * 8] = rb0; \
    *(uint4*)&Bs[bf][(r_ld + 64) * APITCH + seg * 8] = rb1; \
} while (0)

    LOADSTEP(0);
    STORESTEP(0);

    for (int i = 0; i < nsteps; i++) {
        __syncthreads();
        int buf = i & 1;
        bool more = (i + 1 < nsteps);
        if (more) LOADSTEP(i + 1);
        // compute from smem[buf]
#pragma unroll
        for (int kk = 0; kk < 2; kk++) {
            uint32_t af[4][4];
#pragma unroll
            for (int mi = 0; mi < 4; mi++) {
                uint32_t ad = aBase + buf * BUFB + mi * (16 * APITCH * 2) + kk * 32;
                LDSM4(af[mi][0], af[mi][1], af[mi][2], af[mi][3], ad);
            }
            uint32_t bfr[4][2];
#pragma unroll
            for (int g = 0; g < 2; g++) {
                uint32_t t0, t1, t2, t3;
                uint32_t bd = bBase + buf * BUFB + g * (16 * APITCH * 2) + kk * 32;
                LDSM4(t0, t1, t2, t3, bd);
                bfr[2 * g][0] = t0; bfr[2 * g][1] = t1;
                bfr[2 * g + 1][0] = t2; bfr[2 * g + 1][1] = t3;
            }
#pragma unroll
            for (int mi = 0; mi < 4; mi++)
#pragma unroll
                for (int ni = 0; ni < 4; ni++)
                    MMA16816(acc[mi][ni], af[mi], bfr[ni]);
        }
        if (more) STORESTEP(buf ^ 1);
    }

    // epilogue
#pragma unroll
    for (int mi = 0; mi < 4; mi++) {
        int r0 = m0 + wm * 64 + mi * 16 + (lane >> 2);
#pragma unroll
        for (int ni = 0; ni < 4; ni++) {
            int c0 = n0 + wn * 32 + ni * 8 + (lane & 3) * 2;
            float* cr0 = C + (size_t)r0 * Cs;
            float* cr1 = C + (size_t)(r0 + 8) * Cs;
            const float* rr0 = res + (size_t)r0 * Cs;
            const float* rr1 = res + (size_t)(r0 + 8) * Cs;
            if (c0 < Nact) {
                float v0 = acc[mi][ni][0] + bias[c0];
                float v2 = acc[mi][ni][2] + bias[c0];
                if (RES) { v0 += rr0[c0]; v2 += rr1[c0]; }
                cr0[c0] = v0; cr1[c0] = v2;
            }
            if (c0 + 1 < Nact) {
                float v1 = acc[mi][ni][1] + bias[c0 + 1];
                float v3 = acc[mi][ni][3] + bias[c0 + 1];
                if (RES) { v1 += rr0[c0 + 1]; v3 += rr1[c0 + 1]; }
                cr0[c0 + 1] = v1; cr1[c0 + 1] = v3;
            }
        }
    }
}

// ---------------- weight conversion: W[K,N] -> B2[Npad, 2*Kpad] ------------
__global__ void convB_kernel(const float* __restrict__ W, __nv_bfloat16* __restrict__ dst,
                             int K, int N, int Kpad) {
    __shared__ float t[32][33];
    int k0 = blockIdx.x * 32, n0 = blockIdx.y * 32;
    int tx = threadIdx.x, ty = threadIdx.y;
#pragma unroll
    for (int i = 0; i < 4; i++) {
        int k = k0 + ty + i * 8, n = n0 + tx;
        t[ty + i * 8][tx] = (k < K && n < N) ? W[(size_t)k * N + n] : 0.f;
    }
    __syncthreads();
#pragma unroll
    for (int i = 0; i < 4; i++) {
        int n = n0 + ty + i * 8, k = k0 + tx;
        float v = t[tx][ty + i * 8];
        __nv_bfloat16 hi, lo; split_bf16(v, hi, lo);
        dst[(size_t)n * 2 * Kpad + k] = hi;
        dst[(size_t)n * 2 * Kpad + Kpad + k] = lo;
    }
}

// ---------------- A conversion (layer 0 only) ------------------------------
__global__ void convA_kernel(const float* __restrict__ src, __nv_bfloat16* __restrict__ dst) {
    int m = blockIdx.x;
    const float* s = src + (size_t)m * EMBD;
    __nv_bfloat16* d = dst + (size_t)m * 1024;
    for (int k = threadIdx.x; k < 512; k += 128) {
        __nv_bfloat16 hi, lo; split_bf16(s[k], hi, lo);
        d[k] = hi; d[512 + k] = lo;
    }
}

// ---------------- tokenizer ------------------------------------------------
__global__ void tokenizer_kernel(const float* __restrict__ x,
                                 const float* __restrict__ tok_w,
                                 const float* __restrict__ tok_b,
                                 const float* __restrict__ cat_emb,
                                 float* __restrict__ h) {
    int t = blockIdx.x;
    int b = t / SEQ, s = t % SEQ;
    int e0 = threadIdx.x;
    const float* src;
    float scale = 1.0f;
    const float* brow = nullptr;
    if (s == 0) {
        src = tok_w;
    } else if (s <= NCONT) {
        src = tok_w + (size_t)s * EMBD;
        scale = x[(size_t)b * (NCAT + NCONT) + NCAT + (s - 1)];
        brow = tok_b + (size_t)(s - 1) * EMBD;
    } else {
        int c = s - (NCONT + 1);
        int idx = (int)x[(size_t)b * (NCAT + NCONT) + c] + 100 * c;
        src = cat_emb + (size_t)idx * EMBD;
        brow = tok_b + (size_t)(s - 1) * EMBD;
    }
    float* dst = h + (size_t)t * EMBD;
#pragma unroll
    for (int i = 0; i < 4; i++) {
        int e = e0 + i * 128;
        float v = src[e] * scale;
        if (brow) v += brow[e];
        dst[e] = v;
    }
}

// ---------------- layernorm -> bf16 hi/lo ----------------------------------
__global__ void ln_conv_kernel(const float* __restrict__ in,
                               const float* __restrict__ g,
                               const float* __restrict__ b,
                               __nv_bfloat16* __restrict__ out) {
    int row = blockIdx.x * 8 + threadIdx.y;
    if (row >= NTOK) return;
    const float* p = in + (size_t)row * EMBD;
    int lane = threadIdx.x;
    float v[16];
    float s = 0.f;
#pragma unroll
    for (int i = 0; i < 16; i++) { v[i] = p[lane + 32 * i]; s += v[i]; }
#pragma unroll
    for (int o = 16; o; o >>= 1) s += __shfl_xor_sync(0xffffffffu, s, o);
    float mean = s * (1.0f / EMBD);
    float vs = 0.f;
#pragma unroll
    for (int i = 0; i < 16; i++) { float d = v[i] - mean; vs += d * d; }
#pragma unroll
    for (int o = 16; o; o >>= 1) vs += __shfl_xor_sync(0xffffffffu, vs, o);
    float inv = rsqrtf(vs * (1.0f / EMBD) + 1e-5f);
    __nv_bfloat16* qo = out + (size_t)row * 1024;
#pragma unroll
    for (int i = 0; i < 16; i++) {
        int e = lane + 32 * i;
        float y = (v[i] - mean) * inv * g[e] + b[e];
        __nv_bfloat16 hi, lo; split_bf16(y, hi, lo);
        qo[e] = hi; qo[512 + e] = lo;
    }
}

// ---------------- attention scores -----------------------------------------
__global__ void scores_kernel(const float* __restrict__ qkv,
                              float* __restrict__ scores) {
    extern __shared__ float sm[];
    float* qs = sm;
    float* ks = sm + SEQ * 65;
    int bh = blockIdx.x;
    int b = bh / NHEADS, h = bh % NHEADS;
    const float* basep = qkv + (size_t)b * SEQ * QKVN + h * (3 * HDIM);
    int tid = threadIdx.x;
    for (int i = tid; i < SEQ * HDIM; i += 256) {
        int r = i / HDIM, d = i % HDIM;
        const float* row = basep + (size_t)r * QKVN;
        qs[r * 65 + d] = row[d];
        ks[r * 65 + d] = row[HDIM + d];
    }
    __syncthreads();
    const float scale = 22.62741699796952f;
    float* out = scores + (size_t)bh * SEQ * SEQ;
    for (int idx = tid; idx < SEQ * SEQ; idx += 256) {
        int i = idx / SEQ, j = idx % SEQ;
        const float* qi = qs + i * 65;
        const float* kj = ks + j * 65;
        float acc = 0.f;
#pragma unroll
        for (int d = 0; d < HDIM; d++) acc += qi[d] * kj[d];
        out[idx] = acc * scale;
    }
}

// ---------------- double softmax -------------------------------------------
__global__ void softmax2_kernel(float* __restrict__ scores) {
    int row = blockIdx.x * 8 + threadIdx.y;
    if (row >= NBH * SEQ) return;
    float* p = scores + (size_t)row * SEQ;
    int lane = threadIdx.x;
    float v[5];
    int cnt = 0;
    float mx = -1e30f;
    for (int j = lane; j < SEQ; j += 32) { v[cnt] = p[j]; mx = fmaxf(mx, v[cnt]); cnt++; }
#pragma unroll
    for (int o = 16; o; o >>= 1) mx = fmaxf(mx, __shfl_xor_sync(0xffffffffu, mx, o));
    float s = 0.f;
    for (int c = 0; c < cnt; c++) { v[c] = __expf(v[c] - mx); s += v[c]; }
#pragma unroll
    for (int o = 16; o; o >>= 1) s += __shfl_xor_sync(0xffffffffu, s, o);
    float inv = 1.0f / s;
    mx = -1e30f;
    for (int c = 0; c < cnt; c++) { v[c] *= inv; mx = fmaxf(mx, v[c]); }
#pragma unroll
    for (int o = 16; o; o >>= 1) mx = fmaxf(mx, __shfl_xor_sync(0xffffffffu, mx, o));
    s = 0.f;
    for (int c = 0; c < cnt; c++) { v[c] = __expf(v[c] - mx); s += v[c]; }
#pragma unroll
    for (int o = 16; o; o >>= 1) s += __shfl_xor_sync(0xffffffffu, s, o);
    inv = 1.0f / s;
    cnt = 0;
    for (int j = lane; j < SEQ; j += 32) { p[j] = v[cnt] * inv; cnt++; }
}

// ---------------- attn @ v -> A2 bf16 hi/lo --------------------------------
__global__ void av_conv_kernel(const float* __restrict__ qkv,
                               const float* __restrict__ scores,
                               __nv_bfloat16* __restrict__ a2) {
    extern __shared__ float sm[];
    float* attn = sm;
    float* vs = sm + SEQ * SEQ;
    int bh = blockIdx.x;
    int b = bh / NHEADS, h = bh % NHEADS;
    const float* vbase = qkv + (size_t)b * SEQ * QKVN + h * (3 * HDIM) + 2 * HDIM;
    int tid = threadIdx.y * 64 + threadIdx.x;
    const float* srow = scores + (size_t)bh * SEQ * SEQ;
    for (int i = tid; i < SEQ * SEQ; i += 256) attn[i] = srow[i];
    for (int i = tid; i < SEQ * HDIM; i += 256) {
        int r = i / HDIM, d = i % HDIM;
        vs[r * HDIM + d] = vbase[(size_t)r * QKVN + d];
    }
    __syncthreads();
    int d = threadIdx.x;
    int col = h * HDIM + d;
    for (int i = threadIdx.y; i < SEQ; i += 4) {
        const float* ar = attn + i * SEQ;
        float acc = 0.f;
        for (int j = 0; j < SEQ; j++) acc += ar[j] * vs[j * HDIM + d];
        __nv_bfloat16 hi, lo; split_bf16(acc, hi, lo);
        __nv_bfloat16* dRow = a2 + ((size_t)b * SEQ + i) * 1024;
        dRow[col] = hi; dRow[512 + col] = lo;
    }
}

// ---------------- ReGLU -> A2 bf16 hi/lo (Kpad=704) ------------------------
__global__ void reglu_conv_kernel(const float* __restrict__ u, __nv_bfloat16* __restrict__ a2) {
    int n = blockIdx.x;
    const float* un = u + (size_t)n * HID2;
    __nv_bfloat16* rn = a2 + (size_t)n * 1408;
    for (int j = threadIdx.x; j < KPAD_H; j += 256) {
        float v = (j < NHID) ? un[j] * fmaxf(un[NHID + j], 0.f) : 0.f;
        __nv_bfloat16 hi, lo; split_bf16(v, hi, lo);
        rn[j] = hi; rn[KPAD_H + j] = lo;
    }
}

// ---------------- extract CLS ----------------------------------------------
__global__ void extract_kernel(const float* __restrict__ h, float* __restrict__ out) {
    int b = blockIdx.x;
    int e = threadIdx.x;
    out[(size_t)b * EMBD + e] = h[(size_t)b * SEQ * EMBD + e];
}

// ---------------- host -----------------------------------------------------
extern "C" void kernel_launch(void* const* d_in, const int* in_sizes, int n_in,
                              void* d_out, int out_size) {
    (void)in_sizes; (void)n_in; (void)out_size;
    const float* x       = (const float*)d_in[0];
    const float* tok_w   = (const float*)d_in[1];
    const float* tok_b   = (const float*)d_in[2];
    const float* cat_emb = (const float*)d_in[3];
    const float* Wqkv    = (const float*)d_in[4];
    const float* bqkv    = (const float*)d_in[5];
    const float* Wout    = (const float*)d_in[6];
    const float* bout    = (const float*)d_in[7];
    const float* W0      = (const float*)d_in[8];
    const float* b0      = (const float*)d_in[9];
    const float* W1      = (const float*)d_in[10];
    const float* b1      = (const float*)d_in[11];
    const float* ln0_g   = (const float*)d_in[12];
    const float* ln0_b   = (const float*)d_in[13];
    const float* ln1_g   = (const float*)d_in[14];
    const float* ln1_b   = (const float*)d_in[15];
    float* out = (float*)d_out;

    float *ph, *pqkv, *pscores, *pu;
    __nv_bfloat16 *pa2, *pb2;
    cudaGetSymbolAddress((void**)&ph, g_h);
    cudaGetSymbolAddress((void**)&pqkv, g_qkv);
    cudaGetSymbolAddress((void**)&pscores, g_scores);
    cudaGetSymbolAddress((void**)&pu, g_u);
    cudaGetSymbolAddress((void**)&pa2, g_a2);
    cudaGetSymbolAddress((void**)&pb2, g_b2);

    const int SCORES_SMEM = 2 * SEQ * 65 * 4;
    const int AV_SMEM = (SEQ * SEQ + SEQ * HDIM) * 4;
    cudaFuncSetAttribute(scores_kernel, cudaFuncAttributeMaxDynamicSharedMemorySize, SCORES_SMEM);
    cudaFuncSetAttribute(av_conv_kernel, cudaFuncAttributeMaxDynamicSharedMemorySize, AV_SMEM);

    // weight conversion (per launch; pads zeroed by convB's guarded loads)
    for (int L = 0; L < NDEPTH; L++) {
        __nv_bfloat16* bq = pb2 + (size_t)L * B2_LAYER;
        __nv_bfloat16* bo = bq + B2_QKV_SZ;
        __nv_bfloat16* b0p = bo + B2_WOUT_SZ;
        __nv_bfloat16* b1p = b0p + B2_W0_SZ;
        convB_kernel<<<dim3(16, 48), dim3(32, 8)>>>(Wqkv + (size_t)L * EMBD * QKVN, bq, 512, 1536, 512);
        convB_kernel<<<dim3(16, 16), dim3(32, 8)>>>(Wout + (size_t)L * EMBD * EMBD, bo, 512, 512, 512);
        convB_kernel<<<dim3(16, 48), dim3(32, 8)>>>(W0 + (size_t)L * EMBD * HID2, b0p, 512, HID2, 512);
        convB_kernel<<<dim3(22, 16), dim3(32, 8)>>>(W1 + (size_t)L * NHID * EMBD, b1p, NHID, 512, KPAD_H);
    }

    tokenizer_kernel<<<NTOK, 128>>>(x, tok_w, tok_b, cat_emb, ph);

    for (int L = 0; L < NDEPTH; L++) {
        __nv_bfloat16* bq = pb2 + (size_t)L * B2_LAYER;
        __nv_bfloat16* bo = bq + B2_QKV_SZ;
        __nv_bfloat16* b0p = bo + B2_WOUT_SZ;
        __nv_bfloat16* b1p = b0p + B2_W0_SZ;

        if (L == 0) {
            convA_kernel<<<NTOK, 128>>>(ph, pa2);
        } else {
            ln_conv_kernel<<<NTOK / 8, dim3(32, 8)>>>(ph, ln0_g + L * EMBD, ln0_b + L * EMBD, pa2);
        }
        gemm_mma<<<dim3(129, 12), 256>>>(pa2, bq, bqkv + (size_t)L * QKVN,
                                         ph, pqkv, QKVN, QKVN, KPAD_E, 0);
        scores_kernel<<<NBH, 256, SCORES_SMEM>>>(pqkv, pscores);
        softmax2_kernel<<<NBH * SEQ / 8, dim3(32, 8)>>>(pscores);
        av_conv_kernel<<<NBH, dim3(64, 4), AV_SMEM>>>(pqkv, pscores, pa2);
        gemm_mma<<<dim3(129, 4), 256>>>(pa2, bo, bout + (size_t)L * EMBD,
                                        ph, ph, EMBD, EMBD, KPAD_E, 1);
        ln_conv_kernel<<<NTOK / 8, dim3(32, 8)>>>(ph, ln1_g + L * EMBD, ln1_b + L * EMBD, pa2);
        gemm_mma<<<dim3(129, 11), 256>>>(pa2, b0p, b0 + (size_t)L * HID2,
                                         ph, pu, HID2, HID2, KPAD_E, 0);
        reglu_conv_kernel<<<NTOK, 256>>>(pu, pa2);
        gemm_mma<<<dim3(129, 4), 256>>>(pa2, b1p, b1 + (size_t)L * EMBD,
                                        ph, ph, EMBD, EMBD, KPAD_H, 1);
    }
    extract_kernel<<<BSZ, EMBD>>>(ph, out);
}